// round 13
// baseline (speedup 1.0000x reference)
#include <cuda_runtime.h>
#include <cuda_fp16.h>
#include <cstdint>

#define SEQ 4096
#define DM  768
#define NH  12
#define HD  64

// ---------------- scratch (no allocations allowed) ----------------
__device__ __half g_xh[SEQ * DM];    // x fp16
__device__ __half g_Wqh[DM * DM];    // weights fp16
__device__ __half g_Wkh[DM * DM];
__device__ __half g_Wvh[DM * DM];
__device__ __half g_Wph[DM * DM];
__device__ __half g_Qh[SEQ * DM];    // Q fp16, pre-scaled by 0.125*log2e
__device__ __half g_Kh[SEQ * DM];    // K fp16
__device__ __half g_Vh[SEQ * DM];    // V fp16 [s][d]
__device__ __half g_Vt[DM * SEQ];    // V fp16 transposed [d][s]
__device__ __half g_att[SEQ * DM];   // attention output fp16
__device__ int    g_unit_ctr;        // flash work-queue counter (reset by transpose_v)

// ---------------- helpers ----------------
__device__ __forceinline__ uint32_t f2h2(float lo, float hi) {
    uint32_t r;
    asm("cvt.rn.f16x2.f32 %0, %2, %1;" : "=r"(r) : "f"(lo), "f"(hi));
    return r;
}
__device__ __forceinline__ float fexp2(float x) {
    float y;
    asm("ex2.approx.ftz.f32 %0, %1;" : "=f"(y) : "f"(x));
    return y;
}
__device__ __forceinline__ uint32_t smem_u32(const void* p) {
    uint32_t a;
    asm("{ .reg .u64 t; cvta.to.shared.u64 t, %1; cvt.u32.u64 %0, t; }" : "=r"(a) : "l"(p));
    return a;
}
__device__ __forceinline__ void ldsm4(uint32_t& r0, uint32_t& r1, uint32_t& r2, uint32_t& r3,
                                      uint32_t addr) {
    asm volatile("ldmatrix.sync.aligned.m8n8.x4.shared.b16 {%0,%1,%2,%3}, [%4];"
                 : "=r"(r0), "=r"(r1), "=r"(r2), "=r"(r3) : "r"(addr));
}
#define CP_ASYNC16(dst, src) \
    asm volatile("cp.async.ca.shared.global [%0], [%1], 16;" :: "r"(dst), "l"(src) : "memory")
#define CP_COMMIT() asm volatile("cp.async.commit_group;" ::: "memory")
#define CP_WAIT0()  asm volatile("cp.async.wait_group 0;" ::: "memory")
#define CP_WAIT2()  asm volatile("cp.async.wait_group 2;" ::: "memory")

// D += A*B  (m16n8k16 fp16, fp32 accumulate)
__device__ __forceinline__ void mma16(float* d,
                                      uint32_t a0, uint32_t a1, uint32_t a2, uint32_t a3,
                                      uint32_t b0, uint32_t b1) {
    asm volatile(
        "mma.sync.aligned.m16n8k16.row.col.f32.f16.f16.f32 "
        "{%0,%1,%2,%3}, {%4,%5,%6,%7}, {%8,%9}, {%0,%1,%2,%3};"
        : "+f"(d[0]), "+f"(d[1]), "+f"(d[2]), "+f"(d[3])
        : "r"(a0), "r"(a1), "r"(a2), "r"(a3), "r"(b0), "r"(b1));
}

#define QK_SCALE 0.1803368801111204f   // 0.125 * log2(e)

// ================= fp32 -> fp16 conversion (x + 4 weights) =================
__global__ __launch_bounds__(256)
void cvt_inputs(const float* __restrict__ x,  const float* __restrict__ Wq,
                const float* __restrict__ Wk, const float* __restrict__ Wv,
                const float* __restrict__ Wp)
{
    const float* src; __half* dst; int n;
    switch (blockIdx.y) {
        case 0:  src = x;  n = SEQ * DM; dst = g_xh;  break;
        case 1:  src = Wq; n = DM * DM;  dst = g_Wqh; break;
        case 2:  src = Wk; n = DM * DM;  dst = g_Wkh; break;
        case 3:  src = Wv; n = DM * DM;  dst = g_Wvh; break;
        default: src = Wp; n = DM * DM;  dst = g_Wph; break;
    }
    int i = (blockIdx.x * 256 + threadIdx.x) * 8;
    if (i >= n) return;
    float4 a = *(const float4*)(src + i);
    float4 b = *(const float4*)(src + i + 4);
    uint4 u = make_uint4(f2h2(a.x, a.y), f2h2(a.z, a.w), f2h2(b.x, b.y), f2h2(b.z, b.w));
    *(uint4*)(dst + i) = u;
}

// ================= fp16 GEMM core (4-stage cp.async): C = A[M,K] * B[N,K]^T =================
#define GS2 20
#define GW  (128 * GS2)                       // words per operand-stage (2560)
#define GEMM_SMEM_BYTES (8 * GW * 4)          // 4 stages x (A+B) = 81920 B

// issue one 128-row x 32-half tile of A and B into stage s
#define GEMM_ISSUE(s, t)                                                                  \
    do {                                                                                  \
        const uint32_t _ad = as_a + ((s) * GW + lw) * 4;                                  \
        const uint32_t _bd = bs_a + ((s) * GW + lw) * 4;                                  \
        const __half* _as = Ap + (size_t)(t) * 32;                                        \
        const __half* _bs = Bp + (size_t)(t) * 32;                                        \
        CP_ASYNC16(_ad,      _as);                                                        \
        CP_ASYNC16(_ad + 16, _as + 8);                                                    \
        CP_ASYNC16(_bd,      _bs);                                                        \
        CP_ASYNC16(_bd + 16, _bs + 8);                                                    \
    } while (0)

#define GEMM_BODY(EPILOGUE)                                                               \
    extern __shared__ uint32_t gsm[];                                                     \
    const uint32_t as_a = smem_u32(gsm);                                                  \
    const uint32_t bs_a = as_a + 4 * GW * 4;                                              \
    const int tid  = threadIdx.x;                                                         \
    const int wid  = tid >> 5;                                                            \
    const int lane = tid & 31;                                                            \
    const int g    = lane >> 2;                                                           \
    const int tg   = lane & 3;                                                            \
    const int wm   = (wid >> 2) * 64;                                                     \
    const int wn   = (wid & 3) * 32;                                                      \
    const int m0   = blockIdx.y * 128;                                                    \
    const int n0   = blockIdx.x * 128;                                                    \
    const int aoff = (wm + (lane & 15)) * GS2 + ((lane >> 4) << 2);                       \
    const int boff = (wn + ((lane >> 4) << 3) + (lane & 7)) * GS2 + (((lane >> 3) & 1) << 2); \
    const int lrow = tid >> 1;                                                            \
    const int lw   = lrow * GS2 + (tid & 1) * 8;                                          \
    const __half* Ap = Ah + (size_t)(m0 + lrow) * K + (tid & 1) * 16;                     \
    const __half* Bp = Bh + (size_t)(n0 + lrow) * K + (tid & 1) * 16;                     \
    const int T = K / 32;                                                                 \
    GEMM_ISSUE(0, 0); CP_COMMIT();                                                        \
    GEMM_ISSUE(1, 1); CP_COMMIT();                                                        \
    GEMM_ISSUE(2, 2); CP_COMMIT();                                                        \
    float acc[4][4][4] = {};                                                              \
    for (int t = 0; t < T; t++) {                                                         \
        CP_WAIT2();                                                                       \
        __syncthreads();                                                                  \
        if (t + 3 < T) GEMM_ISSUE((t + 3) & 3, t + 3);                                    \
        CP_COMMIT();   /* empty groups at tail keep the wait count uniform */             \
        const uint32_t ab = as_a + (t & 3) * GW * 4;                                      \
        const uint32_t bb = bs_a + (t & 3) * GW * 4;                                      \
        _Pragma("unroll")                                                                 \
        for (int ks = 0; ks < 2; ks++) {                                                  \
            const int k0 = ks * 8;                                                        \
            uint32_t af[4][4], bf[2][4];                                                  \
            _Pragma("unroll")                                                             \
            for (int mt = 0; mt < 4; mt++)                                                \
                ldsm4(af[mt][0], af[mt][1], af[mt][2], af[mt][3],                         \
                      ab + (aoff + mt * 16 * GS2 + k0) * 4);                              \
            _Pragma("unroll")                                                             \
            for (int np = 0; np < 2; np++)                                                \
                ldsm4(bf[np][0], bf[np][1], bf[np][2], bf[np][3],                         \
                      bb + (boff + np * 16 * GS2 + k0) * 4);                              \
            _Pragma("unroll")                                                             \
            for (int nt = 0; nt < 4; nt++) {                                              \
                const uint32_t b0 = bf[nt >> 1][(nt & 1) * 2];                            \
                const uint32_t b1 = bf[nt >> 1][(nt & 1) * 2 + 1];                        \
                _Pragma("unroll")                                                         \
                for (int mt = 0; mt < 4; mt++)                                            \
                    mma16(acc[mt][nt], af[mt][0], af[mt][1], af[mt][2], af[mt][3], b0, b1); \
            }                                                                             \
        }                                                                                 \
        __syncthreads();                                                                  \
    }                                                                                     \
    EPILOGUE

__global__ __launch_bounds__(256, 2)
void gemm_qkv(const __half* __restrict__ Ah0,
              __half* __restrict__ C0, __half* __restrict__ C1, __half* __restrict__ C2,
              int M, int N, int K)
{
    const __half* Ah = Ah0;
    const __half* Bh = (blockIdx.z == 0) ? g_Wqh : ((blockIdx.z == 1) ? g_Wkh : g_Wvh);
    __half*       C  = (blockIdx.z == 0) ? C0 : ((blockIdx.z == 1) ? C1 : C2);
    const float   cs = (blockIdx.z == 0) ? QK_SCALE : 1.0f;

    GEMM_BODY({
#pragma unroll
        for (int mt = 0; mt < 4; mt++) {
            const int r0 = m0 + wm + mt * 16 + g;
#pragma unroll
            for (int nt = 0; nt < 4; nt++) {
                const int c = n0 + wn + nt * 8 + tg * 2;
                *(uint32_t*)&C[(size_t)r0 * N + c]       = f2h2(acc[mt][nt][0] * cs, acc[mt][nt][1] * cs);
                *(uint32_t*)&C[(size_t)(r0 + 8) * N + c] = f2h2(acc[mt][nt][2] * cs, acc[mt][nt][3] * cs);
            }
        }
    })
}

__global__ __launch_bounds__(256, 2)
void gemm_proj(const __half* __restrict__ Ah0, float* __restrict__ C,
               int M, int N, int K)
{
    const __half* Ah = Ah0;
    const __half* Bh = g_Wph;

    GEMM_BODY({
#pragma unroll
        for (int mt = 0; mt < 4; mt++) {
            const int r0 = m0 + wm + mt * 16 + g;
#pragma unroll
            for (int nt = 0; nt < 4; nt++) {
                const int c = n0 + wn + nt * 8 + tg * 2;
                *(float2*)&C[(size_t)r0 * N + c]       = make_float2(acc[mt][nt][0], acc[mt][nt][1]);
                *(float2*)&C[(size_t)(r0 + 8) * N + c] = make_float2(acc[mt][nt][2], acc[mt][nt][3]);
            }
        }
    })
}

// ================= V transpose (fp16) + queue reset =================
__global__ __launch_bounds__(256)
void transpose_v(const __half* __restrict__ V, __half* __restrict__ Vt)
{
    if (blockIdx.x == 0 && blockIdx.y == 0 && threadIdx.x == 0)
        g_unit_ctr = 0;

    __shared__ __half t[32][34];
    const int bx = blockIdx.x * 32;
    const int by = blockIdx.y * 32;
    const int tx = threadIdx.x & 31;
    const int ty = threadIdx.x >> 5;
#pragma unroll
    for (int i = 0; i < 32; i += 8)
        t[ty + i][tx] = V[(size_t)(by + ty + i) * DM + bx + tx];
    __syncthreads();
#pragma unroll
    for (int i = 0; i < 32; i += 8)
        Vt[(size_t)(bx + ty + i) * SEQ + by + tx] = t[tx][ty + i];
}

// ================= Flash attention (fp16, cp.async, persistent LPT, ldmatrix) =================
#define FS 36
#define SM_Q  0
#define SM_K  (128 * FS)
#define SM_V  (SM_K + 2 * 64 * FS)
#define SM_P  (SM_V + 2 * 64 * FS)
#define KVW   (64 * FS)
#define FLASH_SMEM_WORDS (SM_P + 128 * FS)   // 18432 words = 73728 B
#define N_UNITS (32 * NH)
#define FLASH_GRID 444                        // 3 CTAs/SM x 148 SMs

__global__ __launch_bounds__(128, 3)
void flash_tc(const __half* __restrict__ Qh, const __half* __restrict__ Kh,
              const __half* __restrict__ Vt, __half* __restrict__ O)
{
    extern __shared__ uint32_t sm[];
    __shared__ int s_unit;
    uint32_t* Ps = sm + SM_P;

    const uint32_t qs_a = smem_u32(sm + SM_Q);
    const uint32_t ks_a = smem_u32(sm + SM_K);
    const uint32_t vs_a = smem_u32(sm + SM_V);
    const uint32_t ps_a = smem_u32(Ps);

    const int tid  = threadIdx.x;
    const int lane = tid & 31;
    const int g    = lane >> 2;
    const int tg   = lane & 3;
    const int wm   = (tid >> 5) * 32;

    const int krow = tid >> 1;
    const int kch  = (tid & 1) * 32;
    const int kww  = (tid & 1) * 16;

    const int a_off = (wm + (lane & 15)) * FS + ((lane >> 4) << 2);
    const int b_off = (((lane >> 4) << 3) + (lane & 7)) * FS + (((lane >> 3) & 1) << 2);

    for (;;) {
        if (tid == 0) s_unit = atomicAdd(&g_unit_ctr, 1);
        __syncthreads();
        const int u = s_unit;
        if (u >= N_UNITS) return;
        const int qt = 31 - u / NH;
        const int h  = u % NH;

        const __half* krow_p = Kh + (size_t)krow * DM + h * HD + kch;
        const __half* vrow_p = Vt + (size_t)(h * HD + krow) * SEQ + kch;

        {
            const __half* qrow = Qh + (size_t)(qt * 128 + tid) * DM + h * HD;
#pragma unroll
            for (int i = 0; i < 8; i++)
                CP_ASYNC16(qs_a + (tid * FS + i * 4) * 4, qrow + i * 8);
#pragma unroll
            for (int i = 0; i < 4; i++) {
                CP_ASYNC16(ks_a + (krow * FS + kww + i * 4) * 4, krow_p + i * 8);
                CP_ASYNC16(vs_a + (krow * FS + kww + i * 4) * 4, vrow_p + i * 8);
            }
            CP_COMMIT();
        }

        float o[2][8][4] = {};
        float m_[4], l_[4];
#pragma unroll
        for (int i = 0; i < 4; i++) { m_[i] = -1e30f; l_[i] = 0.0f; }

        const int jmax = 2 * qt + 1;

        for (int j = 0; j <= jmax; j++) {
            const int b = j & 1;
            const uint32_t kb = ks_a + b * KVW * 4;
            const uint32_t vb = vs_a + b * KVW * 4;

            CP_WAIT0();
            __syncthreads();

            if (j < jmax) {
                const uint32_t kd = ks_a + ((b ^ 1) * KVW + krow * FS + kww) * 4;
                const uint32_t vd = vs_a + ((b ^ 1) * KVW + krow * FS + kww) * 4;
                const __half* ksrc = krow_p + (size_t)(j + 1) * 64 * DM;
                const __half* vsrc = vrow_p + (size_t)(j + 1) * 64;
#pragma unroll
                for (int i = 0; i < 4; i++) {
                    CP_ASYNC16(kd + i * 16, ksrc + i * 8);
                    CP_ASYNC16(vd + i * 16, vsrc + i * 8);
                }
                CP_COMMIT();
            }

            // ---- S = Q K^T (ldmatrix fragments) ----
            float sv[2][8][4] = {};
#pragma unroll
            for (int ck = 0; ck < 4; ck++) {
                const int k0 = ck * 8;
                uint32_t a[2][4], bf[4][4];
#pragma unroll
                for (int mb = 0; mb < 2; mb++)
                    ldsm4(a[mb][0], a[mb][1], a[mb][2], a[mb][3],
                          qs_a + (a_off + mb * 16 * FS + k0) * 4);
#pragma unroll
                for (int np = 0; np < 4; np++)
                    ldsm4(bf[np][0], bf[np][1], bf[np][2], bf[np][3],
                          kb + (b_off + np * 16 * FS + k0) * 4);
#pragma unroll
                for (int nt = 0; nt < 8; nt++) {
                    const uint32_t b0 = bf[nt >> 1][(nt & 1) * 2];
                    const uint32_t b1 = bf[nt >> 1][(nt & 1) * 2 + 1];
                    mma16(sv[0][nt], a[0][0], a[0][1], a[0][2], a[0][3], b0, b1);
                    mma16(sv[1][nt], a[1][0], a[1][1], a[1][2], a[1][3], b0, b1);
                }
            }

            // ---- causal mask ----
            if (j >= 2 * qt) {
                const int cb = j * 64;
#pragma unroll
                for (int mb = 0; mb < 2; mb++) {
                    const int r0 = qt * 128 + wm + mb * 16 + g, r1 = r0 + 8;
#pragma unroll
                    for (int nt = 0; nt < 8; nt++) {
#pragma unroll
                        for (int cc = 0; cc < 2; cc++) {
                            const int col = cb + nt * 8 + tg * 2 + cc;
                            if (col > r0) sv[mb][nt][cc]     = -1e30f;
                            if (col > r1) sv[mb][nt][2 + cc] = -1e30f;
                        }
                    }
                }
            }

            // ---- online softmax (base-2) ----
#pragma unroll
            for (int mb = 0; mb < 2; mb++) {
                float mx0 = -1e30f, mx1 = -1e30f;
#pragma unroll
                for (int nt = 0; nt < 8; nt++) {
                    mx0 = fmaxf(mx0, fmaxf(sv[mb][nt][0], sv[mb][nt][1]));
                    mx1 = fmaxf(mx1, fmaxf(sv[mb][nt][2], sv[mb][nt][3]));
                }
                mx0 = fmaxf(mx0, __shfl_xor_sync(0xffffffffu, mx0, 1));
                mx0 = fmaxf(mx0, __shfl_xor_sync(0xffffffffu, mx0, 2));
                mx1 = fmaxf(mx1, __shfl_xor_sync(0xffffffffu, mx1, 1));
                mx1 = fmaxf(mx1, __shfl_xor_sync(0xffffffffu, mx1, 2));

                const int g0 = 2 * mb, g1 = 2 * mb + 1;
                const float mn0 = fmaxf(m_[g0], mx0), mn1 = fmaxf(m_[g1], mx1);
                const float al0 = fexp2(m_[g0] - mn0), al1 = fexp2(m_[g1] - mn1);
                float s0 = 0.0f, s1 = 0.0f;
#pragma unroll
                for (int nt = 0; nt < 8; nt++) {
                    sv[mb][nt][0] = fexp2(sv[mb][nt][0] - mn0); s0 += sv[mb][nt][0];
                    sv[mb][nt][1] = fexp2(sv[mb][nt][1] - mn0); s0 += sv[mb][nt][1];
                    sv[mb][nt][2] = fexp2(sv[mb][nt][2] - mn1); s1 += sv[mb][nt][2];
                    sv[mb][nt][3] = fexp2(sv[mb][nt][3] - mn1); s1 += sv[mb][nt][3];
                }
                s0 += __shfl_xor_sync(0xffffffffu, s0, 1);
                s0 += __shfl_xor_sync(0xffffffffu, s0, 2);
                s1 += __shfl_xor_sync(0xffffffffu, s1, 1);
                s1 += __shfl_xor_sync(0xffffffffu, s1, 2);
                l_[g0] = l_[g0] * al0 + s0;  l_[g1] = l_[g1] * al1 + s1;
                m_[g0] = mn0;  m_[g1] = mn1;
#pragma unroll
                for (int nt = 0; nt < 8; nt++) {
                    o[mb][nt][0] *= al0; o[mb][nt][1] *= al0;
                    o[mb][nt][2] *= al1; o[mb][nt][3] *= al1;
                }
            }

            // ---- P to smem (warp-local rows) ----
#pragma unroll
            for (int mb = 0; mb < 2; mb++) {
                const int r = wm + mb * 16 + g;
#pragma unroll
                for (int nt = 0; nt < 8; nt++) {
                    Ps[r * FS + nt * 4 + tg]       = f2h2(sv[mb][nt][0], sv[mb][nt][1]);
                    Ps[(r + 8) * FS + nt * 4 + tg] = f2h2(sv[mb][nt][2], sv[mb][nt][3]);
                }
            }
            __syncwarp();

            // ---- O += P V (ldmatrix fragments) ----
#pragma unroll
            for (int ck = 0; ck < 4; ck++) {
                const int k0 = ck * 8;
                uint32_t a[2][4], bf[4][4];
#pragma unroll
                for (int mb = 0; mb < 2; mb++)
                    ldsm4(a[mb][0], a[mb][1], a[mb][2], a[mb][3],
                          ps_a + (a_off + mb * 16 * FS + k0) * 4);
#pragma unroll
                for (int np = 0; np < 4; np++)
                    ldsm4(bf[np][0], bf[np][1], bf[np][2], bf[np][3],
                          vb + (b_off + np * 16 * FS + k0) * 4);
#pragma unroll
                for (int nt = 0; nt < 8; nt++) {
                    const uint32_t b0 = bf[nt >> 1][(nt & 1) * 2];
                    const uint32_t b1 = bf[nt >> 1][(nt & 1) * 2 + 1];
                    mma16(o[0][nt], a[0][0], a[0][1], a[0][2], a[0][3], b0, b1);
                    mma16(o[1][nt], a[1][0], a[1][1], a[1][2], a[1][3], b0, b1);
                }
            }
        }

        // ---- normalize + store (fp16) ----
#pragma unroll
        for (int mb = 0; mb < 2; mb++) {
            const float i0 = 1.0f / l_[2 * mb], i1 = 1.0f / l_[2 * mb + 1];
            const int r0 = qt * 128 + wm + mb * 16 + g, r1 = r0 + 8;
#pragma unroll
            for (int nt = 0; nt < 8; nt++) {
                const int c = h * HD + nt * 8 + tg * 2;
                *(uint32_t*)&O[(size_t)r0 * DM + c] = f2h2(o[mb][nt][0] * i0, o[mb][nt][1] * i0);
                *(uint32_t*)&O[(size_t)r1 * DM + c] = f2h2(o[mb][nt][2] * i1, o[mb][nt][3] * i1);
            }
        }
    }
}

// ================= launch =================
extern "C" void kernel_launch(void* const* d_in, const int* in_sizes, int n_in,
                              void* d_out, int out_size)
{
    (void)in_sizes; (void)n_in; (void)out_size;
    const float* x  = (const float*)d_in[0];
    const float* Wq = (const float*)d_in[1];
    const float* Wk = (const float*)d_in[2];
    const float* Wv = (const float*)d_in[3];
    const float* Wp = (const float*)d_in[4];
    float* out = (float*)d_out;

    __half *xh, *Qh, *Kh, *Vh, *Vt, *att;
    cudaGetSymbolAddress((void**)&xh,  g_xh);
    cudaGetSymbolAddress((void**)&Qh,  g_Qh);
    cudaGetSymbolAddress((void**)&Kh,  g_Kh);
    cudaGetSymbolAddress((void**)&Vh,  g_Vh);
    cudaGetSymbolAddress((void**)&Vt,  g_Vt);
    cudaGetSymbolAddress((void**)&att, g_att);

    const int flash_smem = FLASH_SMEM_WORDS * (int)sizeof(uint32_t);  // 73728 B
    cudaFuncSetAttribute(flash_tc, cudaFuncAttributeMaxDynamicSharedMemorySize, flash_smem);
    cudaFuncSetAttribute(gemm_qkv, cudaFuncAttributeMaxDynamicSharedMemorySize, GEMM_SMEM_BYTES);
    cudaFuncSetAttribute(gemm_proj, cudaFuncAttributeMaxDynamicSharedMemorySize, GEMM_SMEM_BYTES);

    // fp32 -> fp16 conversion of x + weights
    dim3 gc((SEQ * DM) / (256 * 8), 5);
    cvt_inputs<<<gc, 256>>>(x, Wq, Wk, Wv, Wp);

    // fused QKV projection (fp16 in/out, 4-stage cp.async)
    dim3 gq(DM / 128, SEQ / 128, 3);
    gemm_qkv<<<gq, 256, GEMM_SMEM_BYTES>>>(xh, Qh, Kh, Vh, SEQ, DM, DM);

    // transpose V -> fp16 [D][S] (+ reset flash work queue)
    dim3 gt(DM / 32, SEQ / 32);
    transpose_v<<<gt, 256>>>(Vh, Vt);

    // causal flash attention: persistent LPT queue, 3 CTAs/SM
    flash_tc<<<FLASH_GRID, 128, flash_smem>>>(Qh, Kh, Vt, att);

    // output projection (fp16 in, fp32 out, 4-stage cp.async)
    dim3 gp(DM / 128, SEQ / 128, 1);
    gemm_proj<<<gp, 256, GEMM_SMEM_BYTES>>>(att, out, SEQ, DM, DM);
}

// round 14
// speedup vs baseline: 1.3367x; 1.3367x over previous
#include <cuda_runtime.h>
#include <cuda_fp16.h>
#include <cstdint>

#define SEQ 4096
#define DM  768
#define NH  12
#define HD  64

// ---------------- scratch (no allocations allowed) ----------------
__device__ __half g_xh[SEQ * DM];    // x fp16
__device__ __half g_Wqh[DM * DM];    // weights fp16
__device__ __half g_Wkh[DM * DM];
__device__ __half g_Wvh[DM * DM];
__device__ __half g_Wph[DM * DM];
__device__ __half g_Qh[SEQ * DM];    // Q fp16, pre-scaled by 0.125*log2e
__device__ __half g_Kh[SEQ * DM];    // K fp16
__device__ __half g_Vh[SEQ * DM];    // V fp16 [s][d]
__device__ __half g_Vt[DM * SEQ];    // V fp16 transposed [d][s]
__device__ __half g_att[SEQ * DM];   // attention output fp16
__device__ int    g_unit_ctr;        // flash work-queue counter (reset by transpose_v)

// ---------------- helpers ----------------
__device__ __forceinline__ uint32_t f2h2(float lo, float hi) {
    uint32_t r;
    asm("cvt.rn.f16x2.f32 %0, %2, %1;" : "=r"(r) : "f"(lo), "f"(hi));
    return r;
}
__device__ __forceinline__ float fexp2(float x) {
    float y;
    asm("ex2.approx.ftz.f32 %0, %1;" : "=f"(y) : "f"(x));
    return y;
}
__device__ __forceinline__ uint32_t smem_u32(const void* p) {
    uint32_t a;
    asm("{ .reg .u64 t; cvta.to.shared.u64 t, %1; cvt.u32.u64 %0, t; }" : "=r"(a) : "l"(p));
    return a;
}
__device__ __forceinline__ void ldsm4(uint32_t& r0, uint32_t& r1, uint32_t& r2, uint32_t& r3,
                                      uint32_t addr) {
    asm volatile("ldmatrix.sync.aligned.m8n8.x4.shared.b16 {%0,%1,%2,%3}, [%4];"
                 : "=r"(r0), "=r"(r1), "=r"(r2), "=r"(r3) : "r"(addr));
}
#define CP_ASYNC16(dst, src) \
    asm volatile("cp.async.ca.shared.global [%0], [%1], 16;" :: "r"(dst), "l"(src) : "memory")
#define CP_COMMIT() asm volatile("cp.async.commit_group;" ::: "memory")
#define CP_WAIT0()  asm volatile("cp.async.wait_group 0;" ::: "memory")
#define CP_WAIT2()  asm volatile("cp.async.wait_group 2;" ::: "memory")

// D += A*B  (m16n8k16 fp16, fp32 accumulate)
__device__ __forceinline__ void mma16(float* d,
                                      uint32_t a0, uint32_t a1, uint32_t a2, uint32_t a3,
                                      uint32_t b0, uint32_t b1) {
    asm volatile(
        "mma.sync.aligned.m16n8k16.row.col.f32.f16.f16.f32 "
        "{%0,%1,%2,%3}, {%4,%5,%6,%7}, {%8,%9}, {%0,%1,%2,%3};"
        : "+f"(d[0]), "+f"(d[1]), "+f"(d[2]), "+f"(d[3])
        : "r"(a0), "r"(a1), "r"(a2), "r"(a3), "r"(b0), "r"(b1));
}

#define QK_SCALE 0.1803368801111204f   // 0.125 * log2(e)

// ================= fp32 -> fp16 conversion (x + 4 weights) =================
__global__ __launch_bounds__(256)
void cvt_inputs(const float* __restrict__ x,  const float* __restrict__ Wq,
                const float* __restrict__ Wk, const float* __restrict__ Wv,
                const float* __restrict__ Wp)
{
    const float* src; __half* dst; int n;
    switch (blockIdx.y) {
        case 0:  src = x;  n = SEQ * DM; dst = g_xh;  break;
        case 1:  src = Wq; n = DM * DM;  dst = g_Wqh; break;
        case 2:  src = Wk; n = DM * DM;  dst = g_Wkh; break;
        case 3:  src = Wv; n = DM * DM;  dst = g_Wvh; break;
        default: src = Wp; n = DM * DM;  dst = g_Wph; break;
    }
    int i = (blockIdx.x * 256 + threadIdx.x) * 8;
    if (i >= n) return;
    float4 a = *(const float4*)(src + i);
    float4 b = *(const float4*)(src + i + 4);
    uint4 u = make_uint4(f2h2(a.x, a.y), f2h2(a.z, a.w), f2h2(b.x, b.y), f2h2(b.z, b.w));
    *(uint4*)(dst + i) = u;
}

// ================= fp16 GEMM core (4-stage cp.async): C = A[M,K] * B[N,K]^T =================
#define GS2 20
#define GW  (128 * GS2)                       // words per operand-stage (2560)
#define GEMM_SMEM_BYTES (8 * GW * 4)          // 4 stages x (A+B) = 81920 B

// issue one 128-row x 32-half tile of A and B into stage s
#define GEMM_ISSUE(s, t)                                                                  \
    do {                                                                                  \
        const uint32_t _ad = as_a + ((s) * GW + lw) * 4;                                  \
        const uint32_t _bd = bs_a + ((s) * GW + lw) * 4;                                  \
        const __half* _as = Ap + (size_t)(t) * 32;                                        \
        const __half* _bs = Bp + (size_t)(t) * 32;                                        \
        CP_ASYNC16(_ad,      _as);                                                        \
        CP_ASYNC16(_ad + 16, _as + 8);                                                    \
        CP_ASYNC16(_bd,      _bs);                                                        \
        CP_ASYNC16(_bd + 16, _bs + 8);                                                    \
    } while (0)

#define GEMM_BODY(EPILOGUE)                                                               \
    extern __shared__ uint32_t gsm[];                                                     \
    const uint32_t as_a = smem_u32(gsm);                                                  \
    const uint32_t bs_a = as_a + 4 * GW * 4;                                              \
    const int tid  = threadIdx.x;                                                         \
    const int wid  = tid >> 5;                                                            \
    const int lane = tid & 31;                                                            \
    const int g    = lane >> 2;                                                           \
    const int tg   = lane & 3;                                                            \
    const int wm   = (wid >> 2) * 64;                                                     \
    const int wn   = (wid & 3) * 32;                                                      \
    const int m0   = blockIdx.y * 128;                                                    \
    const int n0   = blockIdx.x * 128;                                                    \
    const int aoff = (wm + (lane & 15)) * GS2 + ((lane >> 4) << 2);                       \
    const int boff = (wn + ((lane >> 4) << 3) + (lane & 7)) * GS2 + (((lane >> 3) & 1) << 2); \
    const int lrow = tid >> 1;                                                            \
    const int lw   = lrow * GS2 + (tid & 1) * 8;                                          \
    const __half* Ap = Ah + (size_t)(m0 + lrow) * K + (tid & 1) * 16;                     \
    const __half* Bp = Bh + (size_t)(n0 + lrow) * K + (tid & 1) * 16;                     \
    const int T = K / 32;                                                                 \
    GEMM_ISSUE(0, 0); CP_COMMIT();                                                        \
    GEMM_ISSUE(1, 1); CP_COMMIT();                                                        \
    GEMM_ISSUE(2, 2); CP_COMMIT();                                                        \
    float acc[4][4][4] = {};                                                              \
    for (int t = 0; t < T; t++) {                                                         \
        CP_WAIT2();                                                                       \
        __syncthreads();                                                                  \
        if (t + 3 < T) GEMM_ISSUE((t + 3) & 3, t + 3);                                    \
        CP_COMMIT();   /* empty groups at tail keep the wait count uniform */             \
        const uint32_t ab = as_a + (t & 3) * GW * 4;                                      \
        const uint32_t bb = bs_a + (t & 3) * GW * 4;                                      \
        _Pragma("unroll")                                                                 \
        for (int ks = 0; ks < 2; ks++) {                                                  \
            const int k0 = ks * 8;                                                        \
            uint32_t af[4][4], bf[2][4];                                                  \
            _Pragma("unroll")                                                             \
            for (int mt = 0; mt < 4; mt++)                                                \
                ldsm4(af[mt][0], af[mt][1], af[mt][2], af[mt][3],                         \
                      ab + (aoff + mt * 16 * GS2 + k0) * 4);                              \
            _Pragma("unroll")                                                             \
            for (int np = 0; np < 2; np++)                                                \
                ldsm4(bf[np][0], bf[np][1], bf[np][2], bf[np][3],                         \
                      bb + (boff + np * 16 * GS2 + k0) * 4);                              \
            _Pragma("unroll")                                                             \
            for (int nt = 0; nt < 4; nt++) {                                              \
                const uint32_t b0 = bf[nt >> 1][(nt & 1) * 2];                            \
                const uint32_t b1 = bf[nt >> 1][(nt & 1) * 2 + 1];                        \
                _Pragma("unroll")                                                         \
                for (int mt = 0; mt < 4; mt++)                                            \
                    mma16(acc[mt][nt], af[mt][0], af[mt][1], af[mt][2], af[mt][3], b0, b1); \
            }                                                                             \
        }                                                                                 \
        __syncthreads();                                                                  \
    }                                                                                     \
    EPILOGUE

__global__ __launch_bounds__(256, 2)
void gemm_qkv(const __half* __restrict__ Ah0,
              __half* __restrict__ C0, __half* __restrict__ C1, __half* __restrict__ C2,
              int M, int N, int K)
{
    const __half* Ah = Ah0;
    const __half* Bh = (blockIdx.z == 0) ? g_Wqh : ((blockIdx.z == 1) ? g_Wkh : g_Wvh);
    __half*       C  = (blockIdx.z == 0) ? C0 : ((blockIdx.z == 1) ? C1 : C2);
    const float   cs = (blockIdx.z == 0) ? QK_SCALE : 1.0f;

    GEMM_BODY({
#pragma unroll
        for (int mt = 0; mt < 4; mt++) {
            const int r0 = m0 + wm + mt * 16 + g;
#pragma unroll
            for (int nt = 0; nt < 4; nt++) {
                const int c = n0 + wn + nt * 8 + tg * 2;
                *(uint32_t*)&C[(size_t)r0 * N + c]       = f2h2(acc[mt][nt][0] * cs, acc[mt][nt][1] * cs);
                *(uint32_t*)&C[(size_t)(r0 + 8) * N + c] = f2h2(acc[mt][nt][2] * cs, acc[mt][nt][3] * cs);
            }
        }
    })
}

__global__ __launch_bounds__(256, 2)
void gemm_proj(const __half* __restrict__ Ah0, float* __restrict__ C,
               int M, int N, int K)
{
    const __half* Ah = Ah0;
    const __half* Bh = g_Wph;

    GEMM_BODY({
#pragma unroll
        for (int mt = 0; mt < 4; mt++) {
            const int r0 = m0 + wm + mt * 16 + g;
#pragma unroll
            for (int nt = 0; nt < 4; nt++) {
                const int c = n0 + wn + nt * 8 + tg * 2;
                *(float2*)&C[(size_t)r0 * N + c]       = make_float2(acc[mt][nt][0], acc[mt][nt][1]);
                *(float2*)&C[(size_t)(r0 + 8) * N + c] = make_float2(acc[mt][nt][2], acc[mt][nt][3]);
            }
        }
    })
}

// ================= V transpose (fp16) + queue reset =================
__global__ __launch_bounds__(256)
void transpose_v(const __half* __restrict__ V, __half* __restrict__ Vt)
{
    if (blockIdx.x == 0 && blockIdx.y == 0 && threadIdx.x == 0)
        g_unit_ctr = 0;

    __shared__ __half t[32][34];
    const int bx = blockIdx.x * 32;
    const int by = blockIdx.y * 32;
    const int tx = threadIdx.x & 31;
    const int ty = threadIdx.x >> 5;
#pragma unroll
    for (int i = 0; i < 32; i += 8)
        t[ty + i][tx] = V[(size_t)(by + ty + i) * DM + bx + tx];
    __syncthreads();
#pragma unroll
    for (int i = 0; i < 32; i += 8)
        Vt[(size_t)(bx + ty + i) * SEQ + by + tx] = t[tx][ty + i];
}

// ================= Flash attention (fp16, cp.async, persistent LPT, ldmatrix) =================
#define FS 36
#define SM_Q  0
#define SM_K  (128 * FS)
#define SM_V  (SM_K + 2 * 64 * FS)
#define SM_P  (SM_V + 2 * 64 * FS)
#define KVW   (64 * FS)
#define FLASH_SMEM_WORDS (SM_P + 128 * FS)   // 18432 words = 73728 B
#define N_UNITS (32 * NH)
#define FLASH_GRID 296                        // 2 CTAs/SM x 148 SMs

__global__ __launch_bounds__(128, 2)
void flash_tc(const __half* __restrict__ Qh, const __half* __restrict__ Kh,
              const __half* __restrict__ Vt, __half* __restrict__ O)
{
    extern __shared__ uint32_t sm[];
    __shared__ int s_unit;
    uint32_t* Ps = sm + SM_P;

    const uint32_t qs_a = smem_u32(sm + SM_Q);
    const uint32_t ks_a = smem_u32(sm + SM_K);
    const uint32_t vs_a = smem_u32(sm + SM_V);
    const uint32_t ps_a = smem_u32(Ps);

    const int tid  = threadIdx.x;
    const int lane = tid & 31;
    const int g    = lane >> 2;
    const int tg   = lane & 3;
    const int wm   = (tid >> 5) * 32;

    const int krow = tid >> 1;
    const int kch  = (tid & 1) * 32;
    const int kww  = (tid & 1) * 16;

    const int a_off = (wm + (lane & 15)) * FS + ((lane >> 4) << 2);
    const int b_off = (((lane >> 4) << 3) + (lane & 7)) * FS + (((lane >> 3) & 1) << 2);

    for (;;) {
        if (tid == 0) s_unit = atomicAdd(&g_unit_ctr, 1);
        __syncthreads();
        const int u = s_unit;
        if (u >= N_UNITS) return;
        const int qt = 31 - u / NH;
        const int h  = u % NH;

        const __half* krow_p = Kh + (size_t)krow * DM + h * HD + kch;
        const __half* vrow_p = Vt + (size_t)(h * HD + krow) * SEQ + kch;

        {
            const __half* qrow = Qh + (size_t)(qt * 128 + tid) * DM + h * HD;
#pragma unroll
            for (int i = 0; i < 8; i++)
                CP_ASYNC16(qs_a + (tid * FS + i * 4) * 4, qrow + i * 8);
#pragma unroll
            for (int i = 0; i < 4; i++) {
                CP_ASYNC16(ks_a + (krow * FS + kww + i * 4) * 4, krow_p + i * 8);
                CP_ASYNC16(vs_a + (krow * FS + kww + i * 4) * 4, vrow_p + i * 8);
            }
            CP_COMMIT();
        }

        float o[2][8][4] = {};
        float m_[4], l_[4];
#pragma unroll
        for (int i = 0; i < 4; i++) { m_[i] = -1e30f; l_[i] = 0.0f; }

        const int jmax = 2 * qt + 1;

        for (int j = 0; j <= jmax; j++) {
            const int b = j & 1;
            const uint32_t kb = ks_a + b * KVW * 4;
            const uint32_t vb = vs_a + b * KVW * 4;

            CP_WAIT0();
            __syncthreads();

            if (j < jmax) {
                const uint32_t kd = ks_a + ((b ^ 1) * KVW + krow * FS + kww) * 4;
                const uint32_t vd = vs_a + ((b ^ 1) * KVW + krow * FS + kww) * 4;
                const __half* ksrc = krow_p + (size_t)(j + 1) * 64 * DM;
                const __half* vsrc = vrow_p + (size_t)(j + 1) * 64;
#pragma unroll
                for (int i = 0; i < 4; i++) {
                    CP_ASYNC16(kd + i * 16, ksrc + i * 8);
                    CP_ASYNC16(vd + i * 16, vsrc + i * 8);
                }
                CP_COMMIT();
            }

            // ---- S = Q K^T (ldmatrix fragments) ----
            float sv[2][8][4] = {};
#pragma unroll
            for (int ck = 0; ck < 4; ck++) {
                const int k0 = ck * 8;
                uint32_t a[2][4], bf[4][4];
#pragma unroll
                for (int mb = 0; mb < 2; mb++)
                    ldsm4(a[mb][0], a[mb][1], a[mb][2], a[mb][3],
                          qs_a + (a_off + mb * 16 * FS + k0) * 4);
#pragma unroll
                for (int np = 0; np < 4; np++)
                    ldsm4(bf[np][0], bf[np][1], bf[np][2], bf[np][3],
                          kb + (b_off + np * 16 * FS + k0) * 4);
#pragma unroll
                for (int nt = 0; nt < 8; nt++) {
                    const uint32_t b0 = bf[nt >> 1][(nt & 1) * 2];
                    const uint32_t b1 = bf[nt >> 1][(nt & 1) * 2 + 1];
                    mma16(sv[0][nt], a[0][0], a[0][1], a[0][2], a[0][3], b0, b1);
                    mma16(sv[1][nt], a[1][0], a[1][1], a[1][2], a[1][3], b0, b1);
                }
            }

            // ---- causal mask ----
            if (j >= 2 * qt) {
                const int cb = j * 64;
#pragma unroll
                for (int mb = 0; mb < 2; mb++) {
                    const int r0 = qt * 128 + wm + mb * 16 + g, r1 = r0 + 8;
#pragma unroll
                    for (int nt = 0; nt < 8; nt++) {
#pragma unroll
                        for (int cc = 0; cc < 2; cc++) {
                            const int col = cb + nt * 8 + tg * 2 + cc;
                            if (col > r0) sv[mb][nt][cc]     = -1e30f;
                            if (col > r1) sv[mb][nt][2 + cc] = -1e30f;
                        }
                    }
                }
            }

            // ---- online softmax (base-2) ----
#pragma unroll
            for (int mb = 0; mb < 2; mb++) {
                float mx0 = -1e30f, mx1 = -1e30f;
#pragma unroll
                for (int nt = 0; nt < 8; nt++) {
                    mx0 = fmaxf(mx0, fmaxf(sv[mb][nt][0], sv[mb][nt][1]));
                    mx1 = fmaxf(mx1, fmaxf(sv[mb][nt][2], sv[mb][nt][3]));
                }
                mx0 = fmaxf(mx0, __shfl_xor_sync(0xffffffffu, mx0, 1));
                mx0 = fmaxf(mx0, __shfl_xor_sync(0xffffffffu, mx0, 2));
                mx1 = fmaxf(mx1, __shfl_xor_sync(0xffffffffu, mx1, 1));
                mx1 = fmaxf(mx1, __shfl_xor_sync(0xffffffffu, mx1, 2));

                const int g0 = 2 * mb, g1 = 2 * mb + 1;
                const float mn0 = fmaxf(m_[g0], mx0), mn1 = fmaxf(m_[g1], mx1);
                const float al0 = fexp2(m_[g0] - mn0), al1 = fexp2(m_[g1] - mn1);
                float s0 = 0.0f, s1 = 0.0f;
#pragma unroll
                for (int nt = 0; nt < 8; nt++) {
                    sv[mb][nt][0] = fexp2(sv[mb][nt][0] - mn0); s0 += sv[mb][nt][0];
                    sv[mb][nt][1] = fexp2(sv[mb][nt][1] - mn0); s0 += sv[mb][nt][1];
                    sv[mb][nt][2] = fexp2(sv[mb][nt][2] - mn1); s1 += sv[mb][nt][2];
                    sv[mb][nt][3] = fexp2(sv[mb][nt][3] - mn1); s1 += sv[mb][nt][3];
                }
                s0 += __shfl_xor_sync(0xffffffffu, s0, 1);
                s0 += __shfl_xor_sync(0xffffffffu, s0, 2);
                s1 += __shfl_xor_sync(0xffffffffu, s1, 1);
                s1 += __shfl_xor_sync(0xffffffffu, s1, 2);
                l_[g0] = l_[g0] * al0 + s0;  l_[g1] = l_[g1] * al1 + s1;
                m_[g0] = mn0;  m_[g1] = mn1;
#pragma unroll
                for (int nt = 0; nt < 8; nt++) {
                    o[mb][nt][0] *= al0; o[mb][nt][1] *= al0;
                    o[mb][nt][2] *= al1; o[mb][nt][3] *= al1;
                }
            }

            // ---- P to smem (warp-local rows) ----
#pragma unroll
            for (int mb = 0; mb < 2; mb++) {
                const int r = wm + mb * 16 + g;
#pragma unroll
                for (int nt = 0; nt < 8; nt++) {
                    Ps[r * FS + nt * 4 + tg]       = f2h2(sv[mb][nt][0], sv[mb][nt][1]);
                    Ps[(r + 8) * FS + nt * 4 + tg] = f2h2(sv[mb][nt][2], sv[mb][nt][3]);
                }
            }
            __syncwarp();

            // ---- O += P V (ldmatrix fragments) ----
#pragma unroll
            for (int ck = 0; ck < 4; ck++) {
                const int k0 = ck * 8;
                uint32_t a[2][4], bf[4][4];
#pragma unroll
                for (int mb = 0; mb < 2; mb++)
                    ldsm4(a[mb][0], a[mb][1], a[mb][2], a[mb][3],
                          ps_a + (a_off + mb * 16 * FS + k0) * 4);
#pragma unroll
                for (int np = 0; np < 4; np++)
                    ldsm4(bf[np][0], bf[np][1], bf[np][2], bf[np][3],
                          vb + (b_off + np * 16 * FS + k0) * 4);
#pragma unroll
                for (int nt = 0; nt < 8; nt++) {
                    const uint32_t b0 = bf[nt >> 1][(nt & 1) * 2];
                    const uint32_t b1 = bf[nt >> 1][(nt & 1) * 2 + 1];
                    mma16(o[0][nt], a[0][0], a[0][1], a[0][2], a[0][3], b0, b1);
                    mma16(o[1][nt], a[1][0], a[1][1], a[1][2], a[1][3], b0, b1);
                }
            }
        }

        // ---- normalize + store (fp16) ----
#pragma unroll
        for (int mb = 0; mb < 2; mb++) {
            const float i0 = 1.0f / l_[2 * mb], i1 = 1.0f / l_[2 * mb + 1];
            const int r0 = qt * 128 + wm + mb * 16 + g, r1 = r0 + 8;
#pragma unroll
            for (int nt = 0; nt < 8; nt++) {
                const int c = h * HD + nt * 8 + tg * 2;
                *(uint32_t*)&O[(size_t)r0 * DM + c] = f2h2(o[mb][nt][0] * i0, o[mb][nt][1] * i0);
                *(uint32_t*)&O[(size_t)r1 * DM + c] = f2h2(o[mb][nt][2] * i1, o[mb][nt][3] * i1);
            }
        }
    }
}

// ================= launch =================
extern "C" void kernel_launch(void* const* d_in, const int* in_sizes, int n_in,
                              void* d_out, int out_size)
{
    (void)in_sizes; (void)n_in; (void)out_size;
    const float* x  = (const float*)d_in[0];
    const float* Wq = (const float*)d_in[1];
    const float* Wk = (const float*)d_in[2];
    const float* Wv = (const float*)d_in[3];
    const float* Wp = (const float*)d_in[4];
    float* out = (float*)d_out;

    __half *xh, *Qh, *Kh, *Vh, *Vt, *att;
    cudaGetSymbolAddress((void**)&xh,  g_xh);
    cudaGetSymbolAddress((void**)&Qh,  g_Qh);
    cudaGetSymbolAddress((void**)&Kh,  g_Kh);
    cudaGetSymbolAddress((void**)&Vh,  g_Vh);
    cudaGetSymbolAddress((void**)&Vt,  g_Vt);
    cudaGetSymbolAddress((void**)&att, g_att);

    const int flash_smem = FLASH_SMEM_WORDS * (int)sizeof(uint32_t);  // 73728 B
    cudaFuncSetAttribute(flash_tc, cudaFuncAttributeMaxDynamicSharedMemorySize, flash_smem);
    cudaFuncSetAttribute(gemm_qkv, cudaFuncAttributeMaxDynamicSharedMemorySize, GEMM_SMEM_BYTES);
    cudaFuncSetAttribute(gemm_proj, cudaFuncAttributeMaxDynamicSharedMemorySize, GEMM_SMEM_BYTES);

    // fp32 -> fp16 conversion of x + weights
    dim3 gc((SEQ * DM) / (256 * 8), 5);
    cvt_inputs<<<gc, 256>>>(x, Wq, Wk, Wv, Wp);

    // fused QKV projection (fp16 in/out, 4-stage cp.async)
    dim3 gq(DM / 128, SEQ / 128, 3);
    gemm_qkv<<<gq, 256, GEMM_SMEM_BYTES>>>(xh, Qh, Kh, Vh, SEQ, DM, DM);

    // transpose V -> fp16 [D][S] (+ reset flash work queue)
    dim3 gt(DM / 32, SEQ / 32);
    transpose_v<<<gt, 256>>>(Vh, Vt);

    // causal flash attention: persistent LPT queue, 2 CTAs/SM
    flash_tc<<<FLASH_GRID, 128, flash_smem>>>(Qh, Kh, Vt, att);

    // output projection (fp16 in, fp32 out, 4-stage cp.async)
    dim3 gp(DM / 128, SEQ / 128, 1);
    gemm_proj<<<gp, 256, GEMM_SMEM_BYTES>>>(att, out, SEQ, DM, DM);
}

// round 15
// speedup vs baseline: 1.4206x; 1.0627x over previous
#include <cuda_runtime.h>
#include <cuda_fp16.h>
#include <cstdint>

#define SEQ 4096
#define DM  768
#define NH  12
#define HD  64

// ---------------- scratch (no allocations allowed) ----------------
__device__ __half g_xh[SEQ * DM];    // x fp16
__device__ __half g_Wqh[DM * DM];    // weights fp16
__device__ __half g_Wkh[DM * DM];
__device__ __half g_Wvh[DM * DM];
__device__ __half g_Wph[DM * DM];
__device__ __half g_Qh[SEQ * DM];    // Q fp16, pre-scaled by 0.125*log2e
__device__ __half g_Kh[SEQ * DM];    // K fp16
__device__ __half g_Vh[SEQ * DM];    // V fp16 [s][d]
__device__ __half g_Vt[DM * SEQ];    // V fp16 transposed [d][s]
__device__ __half g_att[SEQ * DM];   // attention output fp16
__device__ int    g_unit_ctr;        // flash work-queue counter (reset by transpose_v)

// ---------------- helpers ----------------
__device__ __forceinline__ uint32_t f2h2(float lo, float hi) {
    uint32_t r;
    asm("cvt.rn.f16x2.f32 %0, %2, %1;" : "=r"(r) : "f"(lo), "f"(hi));
    return r;
}
__device__ __forceinline__ float fexp2(float x) {
    float y;
    asm("ex2.approx.ftz.f32 %0, %1;" : "=f"(y) : "f"(x));
    return y;
}
__device__ __forceinline__ uint32_t smem_u32(const void* p) {
    uint32_t a;
    asm("{ .reg .u64 t; cvta.to.shared.u64 t, %1; cvt.u32.u64 %0, t; }" : "=r"(a) : "l"(p));
    return a;
}
__device__ __forceinline__ void ldsm4(uint32_t& r0, uint32_t& r1, uint32_t& r2, uint32_t& r3,
                                      uint32_t addr) {
    asm volatile("ldmatrix.sync.aligned.m8n8.x4.shared.b16 {%0,%1,%2,%3}, [%4];"
                 : "=r"(r0), "=r"(r1), "=r"(r2), "=r"(r3) : "r"(addr));
}
#define CP_ASYNC16(dst, src) \
    asm volatile("cp.async.ca.shared.global [%0], [%1], 16;" :: "r"(dst), "l"(src) : "memory")
#define CP_COMMIT() asm volatile("cp.async.commit_group;" ::: "memory")
#define CP_WAIT0()  asm volatile("cp.async.wait_group 0;" ::: "memory")
#define CP_WAIT2()  asm volatile("cp.async.wait_group 2;" ::: "memory")

// D += A*B  (m16n8k16 fp16, fp32 accumulate)
__device__ __forceinline__ void mma16(float* d,
                                      uint32_t a0, uint32_t a1, uint32_t a2, uint32_t a3,
                                      uint32_t b0, uint32_t b1) {
    asm volatile(
        "mma.sync.aligned.m16n8k16.row.col.f32.f16.f16.f32 "
        "{%0,%1,%2,%3}, {%4,%5,%6,%7}, {%8,%9}, {%0,%1,%2,%3};"
        : "+f"(d[0]), "+f"(d[1]), "+f"(d[2]), "+f"(d[3])
        : "r"(a0), "r"(a1), "r"(a2), "r"(a3), "r"(b0), "r"(b1));
}

#define QK_SCALE 0.1803368801111204f   // 0.125 * log2(e)

// ================= fp32 -> fp16 conversion (x + 4 weights) =================
__global__ __launch_bounds__(256)
void cvt_inputs(const float* __restrict__ x,  const float* __restrict__ Wq,
                const float* __restrict__ Wk, const float* __restrict__ Wv,
                const float* __restrict__ Wp)
{
    const float* src; __half* dst; int n;
    switch (blockIdx.y) {
        case 0:  src = x;  n = SEQ * DM; dst = g_xh;  break;
        case 1:  src = Wq; n = DM * DM;  dst = g_Wqh; break;
        case 2:  src = Wk; n = DM * DM;  dst = g_Wkh; break;
        case 3:  src = Wv; n = DM * DM;  dst = g_Wvh; break;
        default: src = Wp; n = DM * DM;  dst = g_Wph; break;
    }
    int i = (blockIdx.x * 256 + threadIdx.x) * 8;
    if (i >= n) return;
    float4 a = *(const float4*)(src + i);
    float4 b = *(const float4*)(src + i + 4);
    uint4 u = make_uint4(f2h2(a.x, a.y), f2h2(a.z, a.w), f2h2(b.x, b.y), f2h2(b.z, b.w));
    *(uint4*)(dst + i) = u;
}

// ================= fp16 GEMM core (4-stage cp.async): C = A[M,K] * B[N,K]^T =================
#define GS2 20
#define GW  (128 * GS2)                       // words per operand-stage (2560)
#define GEMM_SMEM_BYTES (8 * GW * 4)          // 4 stages x (A+B) = 81920 B

// issue one 128-row x 32-half tile of A and B into stage s
#define GEMM_ISSUE(s, t)                                                                  \
    do {                                                                                  \
        const uint32_t _ad = as_a + ((s) * GW + lw) * 4;                                  \
        const uint32_t _bd = bs_a + ((s) * GW + lw) * 4;                                  \
        const __half* _as = Ap + (size_t)(t) * 32;                                        \
        const __half* _bs = Bp + (size_t)(t) * 32;                                        \
        CP_ASYNC16(_ad,      _as);                                                        \
        CP_ASYNC16(_ad + 16, _as + 8);                                                    \
        CP_ASYNC16(_bd,      _bs);                                                        \
        CP_ASYNC16(_bd + 16, _bs + 8);                                                    \
    } while (0)

#define GEMM_BODY(EPILOGUE)                                                               \
    extern __shared__ uint32_t gsm[];                                                     \
    const uint32_t as_a = smem_u32(gsm);                                                  \
    const uint32_t bs_a = as_a + 4 * GW * 4;                                              \
    const int tid  = threadIdx.x;                                                         \
    const int wid  = tid >> 5;                                                            \
    const int lane = tid & 31;                                                            \
    const int g    = lane >> 2;                                                           \
    const int tg   = lane & 3;                                                            \
    const int wm   = (wid >> 2) * 64;                                                     \
    const int wn   = (wid & 3) * 32;                                                      \
    const int m0   = blockIdx.y * 128;                                                    \
    const int n0   = blockIdx.x * 128;                                                    \
    const int aoff = (wm + (lane & 15)) * GS2 + ((lane >> 4) << 2);                       \
    const int boff = (wn + ((lane >> 4) << 3) + (lane & 7)) * GS2 + (((lane >> 3) & 1) << 2); \
    const int lrow = tid >> 1;                                                            \
    const int lw   = lrow * GS2 + (tid & 1) * 8;                                          \
    const __half* Ap = Ah + (size_t)(m0 + lrow) * K + (tid & 1) * 16;                     \
    const __half* Bp = Bh + (size_t)(n0 + lrow) * K + (tid & 1) * 16;                     \
    const int T = K / 32;                                                                 \
    GEMM_ISSUE(0, 0); CP_COMMIT();                                                        \
    GEMM_ISSUE(1, 1); CP_COMMIT();                                                        \
    GEMM_ISSUE(2, 2); CP_COMMIT();                                                        \
    float acc[4][4][4] = {};                                                              \
    for (int t = 0; t < T; t++) {                                                         \
        CP_WAIT2();                                                                       \
        __syncthreads();                                                                  \
        if (t + 3 < T) GEMM_ISSUE((t + 3) & 3, t + 3);                                    \
        CP_COMMIT();   /* empty groups at tail keep the wait count uniform */             \
        const uint32_t ab = as_a + (t & 3) * GW * 4;                                      \
        const uint32_t bb = bs_a + (t & 3) * GW * 4;                                      \
        _Pragma("unroll")                                                                 \
        for (int ks = 0; ks < 2; ks++) {                                                  \
            const int k0 = ks * 8;                                                        \
            uint32_t af[4][4], bf[2][4];                                                  \
            _Pragma("unroll")                                                             \
            for (int mt = 0; mt < 4; mt++)                                                \
                ldsm4(af[mt][0], af[mt][1], af[mt][2], af[mt][3],                         \
                      ab + (aoff + mt * 16 * GS2 + k0) * 4);                              \
            _Pragma("unroll")                                                             \
            for (int np = 0; np < 2; np++)                                                \
                ldsm4(bf[np][0], bf[np][1], bf[np][2], bf[np][3],                         \
                      bb + (boff + np * 16 * GS2 + k0) * 4);                              \
            _Pragma("unroll")                                                             \
            for (int nt = 0; nt < 4; nt++) {                                              \
                const uint32_t b0 = bf[nt >> 1][(nt & 1) * 2];                            \
                const uint32_t b1 = bf[nt >> 1][(nt & 1) * 2 + 1];                        \
                _Pragma("unroll")                                                         \
                for (int mt = 0; mt < 4; mt++)                                            \
                    mma16(acc[mt][nt], af[mt][0], af[mt][1], af[mt][2], af[mt][3], b0, b1); \
            }                                                                             \
        }                                                                                 \
        __syncthreads();                                                                  \
    }                                                                                     \
    EPILOGUE

__global__ __launch_bounds__(256, 2)
void gemm_qkv(const __half* __restrict__ Ah0,
              __half* __restrict__ C0, __half* __restrict__ C1, __half* __restrict__ C2,
              int M, int N, int K)
{
    const __half* Ah = Ah0;
    const __half* Bh = (blockIdx.z == 0) ? g_Wqh : ((blockIdx.z == 1) ? g_Wkh : g_Wvh);
    __half*       C  = (blockIdx.z == 0) ? C0 : ((blockIdx.z == 1) ? C1 : C2);
    const float   cs = (blockIdx.z == 0) ? QK_SCALE : 1.0f;

    GEMM_BODY({
#pragma unroll
        for (int mt = 0; mt < 4; mt++) {
            const int r0 = m0 + wm + mt * 16 + g;
#pragma unroll
            for (int nt = 0; nt < 4; nt++) {
                const int c = n0 + wn + nt * 8 + tg * 2;
                *(uint32_t*)&C[(size_t)r0 * N + c]       = f2h2(acc[mt][nt][0] * cs, acc[mt][nt][1] * cs);
                *(uint32_t*)&C[(size_t)(r0 + 8) * N + c] = f2h2(acc[mt][nt][2] * cs, acc[mt][nt][3] * cs);
            }
        }
    })
}

__global__ __launch_bounds__(256, 2)
void gemm_proj(const __half* __restrict__ Ah0, float* __restrict__ C,
               int M, int N, int K)
{
    const __half* Ah = Ah0;
    const __half* Bh = g_Wph;

    GEMM_BODY({
#pragma unroll
        for (int mt = 0; mt < 4; mt++) {
            const int r0 = m0 + wm + mt * 16 + g;
#pragma unroll
            for (int nt = 0; nt < 4; nt++) {
                const int c = n0 + wn + nt * 8 + tg * 2;
                *(float2*)&C[(size_t)r0 * N + c]       = make_float2(acc[mt][nt][0], acc[mt][nt][1]);
                *(float2*)&C[(size_t)(r0 + 8) * N + c] = make_float2(acc[mt][nt][2], acc[mt][nt][3]);
            }
        }
    })
}

// ================= V transpose (fp16) + queue reset =================
__global__ __launch_bounds__(256)
void transpose_v(const __half* __restrict__ V, __half* __restrict__ Vt)
{
    if (blockIdx.x == 0 && blockIdx.y == 0 && threadIdx.x == 0)
        g_unit_ctr = 0;

    __shared__ __half t[32][34];
    const int bx = blockIdx.x * 32;
    const int by = blockIdx.y * 32;
    const int tx = threadIdx.x & 31;
    const int ty = threadIdx.x >> 5;
#pragma unroll
    for (int i = 0; i < 32; i += 8)
        t[ty + i][tx] = V[(size_t)(by + ty + i) * DM + bx + tx];
    __syncthreads();
#pragma unroll
    for (int i = 0; i < 32; i += 8)
        Vt[(size_t)(bx + ty + i) * SEQ + by + tx] = t[tx][ty + i];
}

// ================= Flash attention (fp16, cp.async, persistent LPT, ldmatrix) =================
// P stays in registers: the S C-fragment IS the PV A-fragment for m16n8k16.
#define FS 36
#define SM_Q  0
#define SM_K  (128 * FS)
#define SM_V  (SM_K + 2 * 64 * FS)
#define KVW   (64 * FS)
#define FLASH_SMEM_WORDS (SM_V + 2 * 64 * FS)   // 13824 words = 55296 B
#define N_UNITS (32 * NH)
#define FLASH_GRID 296                          // 2 CTAs/SM x 148 SMs

__global__ __launch_bounds__(128, 2)
void flash_tc(const __half* __restrict__ Qh, const __half* __restrict__ Kh,
              const __half* __restrict__ Vt, __half* __restrict__ O)
{
    extern __shared__ uint32_t sm[];
    __shared__ int s_unit;

    const uint32_t qs_a = smem_u32(sm + SM_Q);
    const uint32_t ks_a = smem_u32(sm + SM_K);
    const uint32_t vs_a = smem_u32(sm + SM_V);

    const int tid  = threadIdx.x;
    const int lane = tid & 31;
    const int g    = lane >> 2;
    const int tg   = lane & 3;
    const int wm   = (tid >> 5) * 32;

    const int krow = tid >> 1;
    const int kch  = (tid & 1) * 32;
    const int kww  = (tid & 1) * 16;

    const int a_off = (wm + (lane & 15)) * FS + ((lane >> 4) << 2);
    const int b_off = (((lane >> 4) << 3) + (lane & 7)) * FS + (((lane >> 3) & 1) << 2);

    for (;;) {
        if (tid == 0) s_unit = atomicAdd(&g_unit_ctr, 1);
        __syncthreads();
        const int u = s_unit;
        if (u >= N_UNITS) return;
        const int qt = 31 - u / NH;
        const int h  = u % NH;

        const __half* krow_p = Kh + (size_t)krow * DM + h * HD + kch;
        const __half* vrow_p = Vt + (size_t)(h * HD + krow) * SEQ + kch;

        {
            const __half* qrow = Qh + (size_t)(qt * 128 + tid) * DM + h * HD;
#pragma unroll
            for (int i = 0; i < 8; i++)
                CP_ASYNC16(qs_a + (tid * FS + i * 4) * 4, qrow + i * 8);
#pragma unroll
            for (int i = 0; i < 4; i++) {
                CP_ASYNC16(ks_a + (krow * FS + kww + i * 4) * 4, krow_p + i * 8);
                CP_ASYNC16(vs_a + (krow * FS + kww + i * 4) * 4, vrow_p + i * 8);
            }
            CP_COMMIT();
        }

        float o[2][8][4] = {};
        float m_[4], l_[4];
#pragma unroll
        for (int i = 0; i < 4; i++) { m_[i] = -1e30f; l_[i] = 0.0f; }

        const int jmax = 2 * qt + 1;

        for (int j = 0; j <= jmax; j++) {
            const int b = j & 1;
            const uint32_t kb = ks_a + b * KVW * 4;
            const uint32_t vb = vs_a + b * KVW * 4;

            CP_WAIT0();
            __syncthreads();

            if (j < jmax) {
                const uint32_t kd = ks_a + ((b ^ 1) * KVW + krow * FS + kww) * 4;
                const uint32_t vd = vs_a + ((b ^ 1) * KVW + krow * FS + kww) * 4;
                const __half* ksrc = krow_p + (size_t)(j + 1) * 64 * DM;
                const __half* vsrc = vrow_p + (size_t)(j + 1) * 64;
#pragma unroll
                for (int i = 0; i < 4; i++) {
                    CP_ASYNC16(kd + i * 16, ksrc + i * 8);
                    CP_ASYNC16(vd + i * 16, vsrc + i * 8);
                }
                CP_COMMIT();
            }

            // ---- S = Q K^T (ldmatrix fragments) ----
            float sv[2][8][4] = {};
#pragma unroll
            for (int ck = 0; ck < 4; ck++) {
                const int k0 = ck * 8;
                uint32_t a[2][4], bf[4][4];
#pragma unroll
                for (int mb = 0; mb < 2; mb++)
                    ldsm4(a[mb][0], a[mb][1], a[mb][2], a[mb][3],
                          qs_a + (a_off + mb * 16 * FS + k0) * 4);
#pragma unroll
                for (int np = 0; np < 4; np++)
                    ldsm4(bf[np][0], bf[np][1], bf[np][2], bf[np][3],
                          kb + (b_off + np * 16 * FS + k0) * 4);
#pragma unroll
                for (int nt = 0; nt < 8; nt++) {
                    const uint32_t b0 = bf[nt >> 1][(nt & 1) * 2];
                    const uint32_t b1 = bf[nt >> 1][(nt & 1) * 2 + 1];
                    mma16(sv[0][nt], a[0][0], a[0][1], a[0][2], a[0][3], b0, b1);
                    mma16(sv[1][nt], a[1][0], a[1][1], a[1][2], a[1][3], b0, b1);
                }
            }

            // ---- causal mask ----
            if (j >= 2 * qt) {
                const int cb = j * 64;
#pragma unroll
                for (int mb = 0; mb < 2; mb++) {
                    const int r0 = qt * 128 + wm + mb * 16 + g, r1 = r0 + 8;
#pragma unroll
                    for (int nt = 0; nt < 8; nt++) {
#pragma unroll
                        for (int cc = 0; cc < 2; cc++) {
                            const int col = cb + nt * 8 + tg * 2 + cc;
                            if (col > r0) sv[mb][nt][cc]     = -1e30f;
                            if (col > r1) sv[mb][nt][2 + cc] = -1e30f;
                        }
                    }
                }
            }

            // ---- online softmax (base-2) ----
#pragma unroll
            for (int mb = 0; mb < 2; mb++) {
                float mx0 = -1e30f, mx1 = -1e30f;
#pragma unroll
                for (int nt = 0; nt < 8; nt++) {
                    mx0 = fmaxf(mx0, fmaxf(sv[mb][nt][0], sv[mb][nt][1]));
                    mx1 = fmaxf(mx1, fmaxf(sv[mb][nt][2], sv[mb][nt][3]));
                }
                mx0 = fmaxf(mx0, __shfl_xor_sync(0xffffffffu, mx0, 1));
                mx0 = fmaxf(mx0, __shfl_xor_sync(0xffffffffu, mx0, 2));
                mx1 = fmaxf(mx1, __shfl_xor_sync(0xffffffffu, mx1, 1));
                mx1 = fmaxf(mx1, __shfl_xor_sync(0xffffffffu, mx1, 2));

                const int g0 = 2 * mb, g1 = 2 * mb + 1;
                const float mn0 = fmaxf(m_[g0], mx0), mn1 = fmaxf(m_[g1], mx1);
                const float al0 = fexp2(m_[g0] - mn0), al1 = fexp2(m_[g1] - mn1);
                float s0 = 0.0f, s1 = 0.0f;
#pragma unroll
                for (int nt = 0; nt < 8; nt++) {
                    sv[mb][nt][0] = fexp2(sv[mb][nt][0] - mn0); s0 += sv[mb][nt][0];
                    sv[mb][nt][1] = fexp2(sv[mb][nt][1] - mn0); s0 += sv[mb][nt][1];
                    sv[mb][nt][2] = fexp2(sv[mb][nt][2] - mn1); s1 += sv[mb][nt][2];
                    sv[mb][nt][3] = fexp2(sv[mb][nt][3] - mn1); s1 += sv[mb][nt][3];
                }
                s0 += __shfl_xor_sync(0xffffffffu, s0, 1);
                s0 += __shfl_xor_sync(0xffffffffu, s0, 2);
                s1 += __shfl_xor_sync(0xffffffffu, s1, 1);
                s1 += __shfl_xor_sync(0xffffffffu, s1, 2);
                l_[g0] = l_[g0] * al0 + s0;  l_[g1] = l_[g1] * al1 + s1;
                m_[g0] = mn0;  m_[g1] = mn1;
#pragma unroll
                for (int nt = 0; nt < 8; nt++) {
                    o[mb][nt][0] *= al0; o[mb][nt][1] *= al0;
                    o[mb][nt][2] *= al1; o[mb][nt][3] *= al1;
                }
            }

            // ---- O += P V : P stays in registers (S C-frag == PV A-frag) ----
#pragma unroll
            for (int ck = 0; ck < 4; ck++) {
                const int k0 = ck * 8;
                uint32_t a[2][4], bf[4][4];
#pragma unroll
                for (int mb = 0; mb < 2; mb++) {
                    a[mb][0] = f2h2(sv[mb][2*ck][0],   sv[mb][2*ck][1]);     // P[g,    16ck+2tg..]
                    a[mb][1] = f2h2(sv[mb][2*ck][2],   sv[mb][2*ck][3]);     // P[g+8,  16ck+2tg..]
                    a[mb][2] = f2h2(sv[mb][2*ck+1][0], sv[mb][2*ck+1][1]);   // P[g,    16ck+8+2tg..]
                    a[mb][3] = f2h2(sv[mb][2*ck+1][2], sv[mb][2*ck+1][3]);   // P[g+8,  16ck+8+2tg..]
                }
#pragma unroll
                for (int np = 0; np < 4; np++)
                    ldsm4(bf[np][0], bf[np][1], bf[np][2], bf[np][3],
                          vb + (b_off + np * 16 * FS + k0) * 4);
#pragma unroll
                for (int nt = 0; nt < 8; nt++) {
                    const uint32_t b0 = bf[nt >> 1][(nt & 1) * 2];
                    const uint32_t b1 = bf[nt >> 1][(nt & 1) * 2 + 1];
                    mma16(o[0][nt], a[0][0], a[0][1], a[0][2], a[0][3], b0, b1);
                    mma16(o[1][nt], a[1][0], a[1][1], a[1][2], a[1][3], b0, b1);
                }
            }
        }

        // ---- normalize + store (fp16) ----
#pragma unroll
        for (int mb = 0; mb < 2; mb++) {
            const float i0 = 1.0f / l_[2 * mb], i1 = 1.0f / l_[2 * mb + 1];
            const int r0 = qt * 128 + wm + mb * 16 + g, r1 = r0 + 8;
#pragma unroll
            for (int nt = 0; nt < 8; nt++) {
                const int c = h * HD + nt * 8 + tg * 2;
                *(uint32_t*)&O[(size_t)r0 * DM + c] = f2h2(o[mb][nt][0] * i0, o[mb][nt][1] * i0);
                *(uint32_t*)&O[(size_t)r1 * DM + c] = f2h2(o[mb][nt][2] * i1, o[mb][nt][3] * i1);
            }
        }
    }
}

// ================= launch =================
extern "C" void kernel_launch(void* const* d_in, const int* in_sizes, int n_in,
                              void* d_out, int out_size)
{
    (void)in_sizes; (void)n_in; (void)out_size;
    const float* x  = (const float*)d_in[0];
    const float* Wq = (const float*)d_in[1];
    const float* Wk = (const float*)d_in[2];
    const float* Wv = (const float*)d_in[3];
    const float* Wp = (const float*)d_in[4];
    float* out = (float*)d_out;

    __half *xh, *Qh, *Kh, *Vh, *Vt, *att;
    cudaGetSymbolAddress((void**)&xh,  g_xh);
    cudaGetSymbolAddress((void**)&Qh,  g_Qh);
    cudaGetSymbolAddress((void**)&Kh,  g_Kh);
    cudaGetSymbolAddress((void**)&Vh,  g_Vh);
    cudaGetSymbolAddress((void**)&Vt,  g_Vt);
    cudaGetSymbolAddress((void**)&att, g_att);

    const int flash_smem = FLASH_SMEM_WORDS * (int)sizeof(uint32_t);  // 55296 B
    cudaFuncSetAttribute(flash_tc, cudaFuncAttributeMaxDynamicSharedMemorySize, flash_smem);
    cudaFuncSetAttribute(gemm_qkv, cudaFuncAttributeMaxDynamicSharedMemorySize, GEMM_SMEM_BYTES);
    cudaFuncSetAttribute(gemm_proj, cudaFuncAttributeMaxDynamicSharedMemorySize, GEMM_SMEM_BYTES);

    // fp32 -> fp16 conversion of x + weights
    dim3 gc((SEQ * DM) / (256 * 8), 5);
    cvt_inputs<<<gc, 256>>>(x, Wq, Wk, Wv, Wp);

    // fused QKV projection (fp16 in/out, 4-stage cp.async)
    dim3 gq(DM / 128, SEQ / 128, 3);
    gemm_qkv<<<gq, 256, GEMM_SMEM_BYTES>>>(xh, Qh, Kh, Vh, SEQ, DM, DM);

    // transpose V -> fp16 [D][S] (+ reset flash work queue)
    dim3 gt(DM / 32, SEQ / 32);
    transpose_v<<<gt, 256>>>(Vh, Vt);

    // causal flash attention: persistent LPT queue, 2 CTAs/SM, register-resident P
    flash_tc<<<FLASH_GRID, 128, flash_smem>>>(Qh, Kh, Vt, att);

    // output projection (fp16 in, fp32 out, 4-stage cp.async)
    dim3 gp(DM / 128, SEQ / 128, 1);
    gemm_proj<<<gp, 256, GEMM_SMEM_BYTES>>>(att, out, SEQ, DM, DM);
}

// round 16
// speedup vs baseline: 1.4652x; 1.0314x over previous
#include <cuda_runtime.h>
#include <cuda_fp16.h>
#include <cstdint>

#define SEQ 4096
#define DM  768
#define NH  12
#define HD  64

// ---------------- scratch (no allocations allowed) ----------------
__device__ __half g_xh[SEQ * DM];    // x fp16
__device__ __half g_Wqh[DM * DM];    // weights fp16
__device__ __half g_Wkh[DM * DM];
__device__ __half g_Wvh[DM * DM];
__device__ __half g_Wph[DM * DM];
__device__ __half g_Qh[SEQ * DM];    // Q fp16, pre-scaled by 0.125*log2e
__device__ __half g_Kh[SEQ * DM];    // K fp16
__device__ __half g_Vh[SEQ * DM];    // V fp16 [s][d]
__device__ __half g_Vt[DM * SEQ];    // V fp16 transposed [d][s]
__device__ __half g_att[SEQ * DM];   // attention output fp16
__device__ int    g_unit_ctr;        // flash work-queue counter (reset by transpose_v)

// ---------------- helpers ----------------
__device__ __forceinline__ uint32_t f2h2(float lo, float hi) {
    uint32_t r;
    asm("cvt.rn.f16x2.f32 %0, %2, %1;" : "=r"(r) : "f"(lo), "f"(hi));
    return r;
}
__device__ __forceinline__ float fexp2(float x) {
    float y;
    asm("ex2.approx.ftz.f32 %0, %1;" : "=f"(y) : "f"(x));
    return y;
}
__device__ __forceinline__ uint32_t smem_u32(const void* p) {
    uint32_t a;
    asm("{ .reg .u64 t; cvta.to.shared.u64 t, %1; cvt.u32.u64 %0, t; }" : "=r"(a) : "l"(p));
    return a;
}
__device__ __forceinline__ void ldsm4(uint32_t& r0, uint32_t& r1, uint32_t& r2, uint32_t& r3,
                                      uint32_t addr) {
    asm volatile("ldmatrix.sync.aligned.m8n8.x4.shared.b16 {%0,%1,%2,%3}, [%4];"
                 : "=r"(r0), "=r"(r1), "=r"(r2), "=r"(r3) : "r"(addr));
}
#define CP_ASYNC16(dst, src) \
    asm volatile("cp.async.ca.shared.global [%0], [%1], 16;" :: "r"(dst), "l"(src) : "memory")
#define CP_COMMIT() asm volatile("cp.async.commit_group;" ::: "memory")
#define CP_WAIT0()  asm volatile("cp.async.wait_group 0;" ::: "memory")
#define CP_WAIT2()  asm volatile("cp.async.wait_group 2;" ::: "memory")

// D += A*B  (m16n8k16 fp16, fp32 accumulate)
__device__ __forceinline__ void mma16(float* d,
                                      uint32_t a0, uint32_t a1, uint32_t a2, uint32_t a3,
                                      uint32_t b0, uint32_t b1) {
    asm volatile(
        "mma.sync.aligned.m16n8k16.row.col.f32.f16.f16.f32 "
        "{%0,%1,%2,%3}, {%4,%5,%6,%7}, {%8,%9}, {%0,%1,%2,%3};"
        : "+f"(d[0]), "+f"(d[1]), "+f"(d[2]), "+f"(d[3])
        : "r"(a0), "r"(a1), "r"(a2), "r"(a3), "r"(b0), "r"(b1));
}

#define QK_SCALE 0.1803368801111204f   // 0.125 * log2(e)

// ================= fp32 -> fp16 conversion (x + 4 weights) =================
__global__ __launch_bounds__(256)
void cvt_inputs(const float* __restrict__ x,  const float* __restrict__ Wq,
                const float* __restrict__ Wk, const float* __restrict__ Wv,
                const float* __restrict__ Wp)
{
    const float* src; __half* dst; int n;
    switch (blockIdx.y) {
        case 0:  src = x;  n = SEQ * DM; dst = g_xh;  break;
        case 1:  src = Wq; n = DM * DM;  dst = g_Wqh; break;
        case 2:  src = Wk; n = DM * DM;  dst = g_Wkh; break;
        case 3:  src = Wv; n = DM * DM;  dst = g_Wvh; break;
        default: src = Wp; n = DM * DM;  dst = g_Wph; break;
    }
    int i = (blockIdx.x * 256 + threadIdx.x) * 8;
    if (i >= n) return;
    float4 a = *(const float4*)(src + i);
    float4 b = *(const float4*)(src + i + 4);
    uint4 u = make_uint4(f2h2(a.x, a.y), f2h2(a.z, a.w), f2h2(b.x, b.y), f2h2(b.z, b.w));
    *(uint4*)(dst + i) = u;
}

// ================= fp16 GEMM core (4-stage cp.async): C = A[M,K] * B[N,K]^T =================
#define GS2 20
#define GW  (128 * GS2)                       // words per operand-stage (2560)
#define GEMM_SMEM_BYTES (8 * GW * 4)          // 4 stages x (A+B) = 81920 B

#define GEMM_ISSUE(s, t)                                                                  \
    do {                                                                                  \
        const uint32_t _ad = as_a + ((s) * GW + lw) * 4;                                  \
        const uint32_t _bd = bs_a + ((s) * GW + lw) * 4;                                  \
        const __half* _as = Ap + (size_t)(t) * 32;                                        \
        const __half* _bs = Bp + (size_t)(t) * 32;                                        \
        CP_ASYNC16(_ad,      _as);                                                        \
        CP_ASYNC16(_ad + 16, _as + 8);                                                    \
        CP_ASYNC16(_bd,      _bs);                                                        \
        CP_ASYNC16(_bd + 16, _bs + 8);                                                    \
    } while (0)

#define GEMM_BODY(EPILOGUE)                                                               \
    extern __shared__ uint32_t gsm[];                                                     \
    const uint32_t as_a = smem_u32(gsm);                                                  \
    const uint32_t bs_a = as_a + 4 * GW * 4;                                              \
    const int tid  = threadIdx.x;                                                         \
    const int wid  = tid >> 5;                                                            \
    const int lane = tid & 31;                                                            \
    const int g    = lane >> 2;                                                           \
    const int tg   = lane & 3;                                                            \
    const int wm   = (wid >> 2) * 64;                                                     \
    const int wn   = (wid & 3) * 32;                                                      \
    const int m0   = blockIdx.y * 128;                                                    \
    const int n0   = blockIdx.x * 128;                                                    \
    const int aoff = (wm + (lane & 15)) * GS2 + ((lane >> 4) << 2);                       \
    const int boff = (wn + ((lane >> 4) << 3) + (lane & 7)) * GS2 + (((lane >> 3) & 1) << 2); \
    const int lrow = tid >> 1;                                                            \
    const int lw   = lrow * GS2 + (tid & 1) * 8;                                          \
    const __half* Ap = Ah + (size_t)(m0 + lrow) * K + (tid & 1) * 16;                     \
    const __half* Bp = Bh + (size_t)(n0 + lrow) * K + (tid & 1) * 16;                     \
    const int T = K / 32;                                                                 \
    GEMM_ISSUE(0, 0); CP_COMMIT();                                                        \
    GEMM_ISSUE(1, 1); CP_COMMIT();                                                        \
    GEMM_ISSUE(2, 2); CP_COMMIT();                                                        \
    float acc[4][4][4] = {};                                                              \
    for (int t = 0; t < T; t++) {                                                         \
        CP_WAIT2();                                                                       \
        __syncthreads();                                                                  \
        if (t + 3 < T) GEMM_ISSUE((t + 3) & 3, t + 3);                                    \
        CP_COMMIT();   /* empty groups at tail keep the wait count uniform */             \
        const uint32_t ab = as_a + (t & 3) * GW * 4;                                      \
        const uint32_t bb = bs_a + (t & 3) * GW * 4;                                      \
        _Pragma("unroll")                                                                 \
        for (int ks = 0; ks < 2; ks++) {                                                  \
            const int k0 = ks * 8;                                                        \
            uint32_t af[4][4], bf[2][4];                                                  \
            _Pragma("unroll")                                                             \
            for (int mt = 0; mt < 4; mt++)                                                \
                ldsm4(af[mt][0], af[mt][1], af[mt][2], af[mt][3],                         \
                      ab + (aoff + mt * 16 * GS2 + k0) * 4);                              \
            _Pragma("unroll")                                                             \
            for (int np = 0; np < 2; np++)                                                \
                ldsm4(bf[np][0], bf[np][1], bf[np][2], bf[np][3],                         \
                      bb + (boff + np * 16 * GS2 + k0) * 4);                              \
            _Pragma("unroll")                                                             \
            for (int nt = 0; nt < 4; nt++) {                                              \
                const uint32_t b0 = bf[nt >> 1][(nt & 1) * 2];                            \
                const uint32_t b1 = bf[nt >> 1][(nt & 1) * 2 + 1];                        \
                _Pragma("unroll")                                                         \
                for (int mt = 0; mt < 4; mt++)                                            \
                    mma16(acc[mt][nt], af[mt][0], af[mt][1], af[mt][2], af[mt][3], b0, b1); \
            }                                                                             \
        }                                                                                 \
        __syncthreads();                                                                  \
    }                                                                                     \
    EPILOGUE

__global__ __launch_bounds__(256, 2)
void gemm_qkv(const __half* __restrict__ Ah0,
              __half* __restrict__ C0, __half* __restrict__ C1, __half* __restrict__ C2,
              int M, int N, int K)
{
    const __half* Ah = Ah0;
    const __half* Bh = (blockIdx.z == 0) ? g_Wqh : ((blockIdx.z == 1) ? g_Wkh : g_Wvh);
    __half*       C  = (blockIdx.z == 0) ? C0 : ((blockIdx.z == 1) ? C1 : C2);
    const float   cs = (blockIdx.z == 0) ? QK_SCALE : 1.0f;

    GEMM_BODY({
#pragma unroll
        for (int mt = 0; mt < 4; mt++) {
            const int r0 = m0 + wm + mt * 16 + g;
#pragma unroll
            for (int nt = 0; nt < 4; nt++) {
                const int c = n0 + wn + nt * 8 + tg * 2;
                *(uint32_t*)&C[(size_t)r0 * N + c]       = f2h2(acc[mt][nt][0] * cs, acc[mt][nt][1] * cs);
                *(uint32_t*)&C[(size_t)(r0 + 8) * N + c] = f2h2(acc[mt][nt][2] * cs, acc[mt][nt][3] * cs);
            }
        }
    })
}

__global__ __launch_bounds__(256, 2)
void gemm_proj(const __half* __restrict__ Ah0, float* __restrict__ C,
               int M, int N, int K)
{
    const __half* Ah = Ah0;
    const __half* Bh = g_Wph;

    GEMM_BODY({
#pragma unroll
        for (int mt = 0; mt < 4; mt++) {
            const int r0 = m0 + wm + mt * 16 + g;
#pragma unroll
            for (int nt = 0; nt < 4; nt++) {
                const int c = n0 + wn + nt * 8 + tg * 2;
                *(float2*)&C[(size_t)r0 * N + c]       = make_float2(acc[mt][nt][0], acc[mt][nt][1]);
                *(float2*)&C[(size_t)(r0 + 8) * N + c] = make_float2(acc[mt][nt][2], acc[mt][nt][3]);
            }
        }
    })
}

// ================= V transpose (fp16) + queue reset =================
__global__ __launch_bounds__(256)
void transpose_v(const __half* __restrict__ V, __half* __restrict__ Vt)
{
    if (blockIdx.x == 0 && blockIdx.y == 0 && threadIdx.x == 0)
        g_unit_ctr = 0;

    __shared__ __half t[32][34];
    const int bx = blockIdx.x * 32;
    const int by = blockIdx.y * 32;
    const int tx = threadIdx.x & 31;
    const int ty = threadIdx.x >> 5;
#pragma unroll
    for (int i = 0; i < 32; i += 8)
        t[ty + i][tx] = V[(size_t)(by + ty + i) * DM + bx + tx];
    __syncthreads();
#pragma unroll
    for (int i = 0; i < 32; i += 8)
        Vt[(size_t)(bx + ty + i) * SEQ + by + tx] = t[tx][ty + i];
}

// ================= Flash attention (fp16, cp.async, persistent LPT, ldmatrix) =================
// P register-resident; Q fragments hoisted out of the KV loop; V fragments software-pipelined.
#define FS 36
#define SM_Q  0
#define SM_K  (128 * FS)
#define SM_V  (SM_K + 2 * 64 * FS)
#define KVW   (64 * FS)
#define FLASH_SMEM_WORDS (SM_V + 2 * 64 * FS)   // 13824 words = 55296 B
#define N_UNITS (32 * NH)
#define FLASH_GRID 296                          // 2 CTAs/SM x 148 SMs

__global__ __launch_bounds__(128, 2)
void flash_tc(const __half* __restrict__ Qh, const __half* __restrict__ Kh,
              const __half* __restrict__ Vt, __half* __restrict__ O)
{
    extern __shared__ uint32_t sm[];
    __shared__ int s_unit;

    const uint32_t qs_a = smem_u32(sm + SM_Q);
    const uint32_t ks_a = smem_u32(sm + SM_K);
    const uint32_t vs_a = smem_u32(sm + SM_V);

    const int tid  = threadIdx.x;
    const int lane = tid & 31;
    const int g    = lane >> 2;
    const int tg   = lane & 3;
    const int wm   = (tid >> 5) * 32;

    const int krow = tid >> 1;
    const int kch  = (tid & 1) * 32;
    const int kww  = (tid & 1) * 16;

    const int a_off = (wm + (lane & 15)) * FS + ((lane >> 4) << 2);
    const int b_off = (((lane >> 4) << 3) + (lane & 7)) * FS + (((lane >> 3) & 1) << 2);

    for (;;) {
        if (tid == 0) s_unit = atomicAdd(&g_unit_ctr, 1);
        __syncthreads();
        const int u = s_unit;
        if (u >= N_UNITS) return;
        const int qt = 31 - u / NH;
        const int h  = u % NH;

        const __half* krow_p = Kh + (size_t)krow * DM + h * HD + kch;
        const __half* vrow_p = Vt + (size_t)(h * HD + krow) * SEQ + kch;

        // ---- prologue: async-copy Q tile + K/V tile 0, wait, hoist Q fragments ----
        {
            const __half* qrow = Qh + (size_t)(qt * 128 + tid) * DM + h * HD;
#pragma unroll
            for (int i = 0; i < 8; i++)
                CP_ASYNC16(qs_a + (tid * FS + i * 4) * 4, qrow + i * 8);
#pragma unroll
            for (int i = 0; i < 4; i++) {
                CP_ASYNC16(ks_a + (krow * FS + kww + i * 4) * 4, krow_p + i * 8);
                CP_ASYNC16(vs_a + (krow * FS + kww + i * 4) * 4, vrow_p + i * 8);
            }
            CP_COMMIT();
        }
        CP_WAIT0();
        __syncthreads();

        uint32_t qf[2][4][4];   // loop-invariant Q fragments [mb][ck][reg]
#pragma unroll
        for (int ck = 0; ck < 4; ck++)
#pragma unroll
            for (int mb = 0; mb < 2; mb++)
                ldsm4(qf[mb][ck][0], qf[mb][ck][1], qf[mb][ck][2], qf[mb][ck][3],
                      qs_a + (a_off + mb * 16 * FS + ck * 8) * 4);

        float o[2][8][4] = {};
        float m_[4], l_[4];
#pragma unroll
        for (int i = 0; i < 4; i++) { m_[i] = -1e30f; l_[i] = 0.0f; }

        const int jmax = 2 * qt + 1;

        for (int j = 0; j <= jmax; j++) {
            const int b = j & 1;
            const uint32_t kb = ks_a + b * KVW * 4;
            const uint32_t vb = vs_a + b * KVW * 4;

            if (j > 0) {
                CP_WAIT0();
                __syncthreads();   // tile j visible; iter j-1's buffer reads complete
            }

            if (j < jmax) {
                const uint32_t kd = ks_a + ((b ^ 1) * KVW + krow * FS + kww) * 4;
                const uint32_t vd = vs_a + ((b ^ 1) * KVW + krow * FS + kww) * 4;
                const __half* ksrc = krow_p + (size_t)(j + 1) * 64 * DM;
                const __half* vsrc = vrow_p + (size_t)(j + 1) * 64;
#pragma unroll
                for (int i = 0; i < 4; i++) {
                    CP_ASYNC16(kd + i * 16, ksrc + i * 8);
                    CP_ASYNC16(vd + i * 16, vsrc + i * 8);
                }
                CP_COMMIT();
            }

            // ---- S = Q K^T (hoisted Q fragments) ----
            float sv[2][8][4] = {};
#pragma unroll
            for (int ck = 0; ck < 4; ck++) {
                const int k0 = ck * 8;
                uint32_t bf[4][4];
#pragma unroll
                for (int np = 0; np < 4; np++)
                    ldsm4(bf[np][0], bf[np][1], bf[np][2], bf[np][3],
                          kb + (b_off + np * 16 * FS + k0) * 4);
#pragma unroll
                for (int nt = 0; nt < 8; nt++) {
                    const uint32_t b0 = bf[nt >> 1][(nt & 1) * 2];
                    const uint32_t b1 = bf[nt >> 1][(nt & 1) * 2 + 1];
                    mma16(sv[0][nt], qf[0][ck][0], qf[0][ck][1], qf[0][ck][2], qf[0][ck][3], b0, b1);
                    mma16(sv[1][nt], qf[1][ck][0], qf[1][ck][1], qf[1][ck][2], qf[1][ck][3], b0, b1);
                }
            }

            // ---- causal mask ----
            if (j >= 2 * qt) {
                const int cb = j * 64;
#pragma unroll
                for (int mb = 0; mb < 2; mb++) {
                    const int r0 = qt * 128 + wm + mb * 16 + g, r1 = r0 + 8;
#pragma unroll
                    for (int nt = 0; nt < 8; nt++) {
#pragma unroll
                        for (int cc = 0; cc < 2; cc++) {
                            const int col = cb + nt * 8 + tg * 2 + cc;
                            if (col > r0) sv[mb][nt][cc]     = -1e30f;
                            if (col > r1) sv[mb][nt][2 + cc] = -1e30f;
                        }
                    }
                }
            }

            // ---- prefetch V ck=0 fragments (LDS latency hides under softmax) ----
            uint32_t vf[2][4][4];
#pragma unroll
            for (int np = 0; np < 4; np++)
                ldsm4(vf[0][np][0], vf[0][np][1], vf[0][np][2], vf[0][np][3],
                      vb + (b_off + np * 16 * FS) * 4);

            // ---- online softmax (base-2) ----
#pragma unroll
            for (int mb = 0; mb < 2; mb++) {
                float mx0 = -1e30f, mx1 = -1e30f;
#pragma unroll
                for (int nt = 0; nt < 8; nt++) {
                    mx0 = fmaxf(mx0, fmaxf(sv[mb][nt][0], sv[mb][nt][1]));
                    mx1 = fmaxf(mx1, fmaxf(sv[mb][nt][2], sv[mb][nt][3]));
                }
                mx0 = fmaxf(mx0, __shfl_xor_sync(0xffffffffu, mx0, 1));
                mx0 = fmaxf(mx0, __shfl_xor_sync(0xffffffffu, mx0, 2));
                mx1 = fmaxf(mx1, __shfl_xor_sync(0xffffffffu, mx1, 1));
                mx1 = fmaxf(mx1, __shfl_xor_sync(0xffffffffu, mx1, 2));

                const int g0 = 2 * mb, g1 = 2 * mb + 1;
                const float mn0 = fmaxf(m_[g0], mx0), mn1 = fmaxf(m_[g1], mx1);
                const float al0 = fexp2(m_[g0] - mn0), al1 = fexp2(m_[g1] - mn1);
                float s0 = 0.0f, s1 = 0.0f;
#pragma unroll
                for (int nt = 0; nt < 8; nt++) {
                    sv[mb][nt][0] = fexp2(sv[mb][nt][0] - mn0); s0 += sv[mb][nt][0];
                    sv[mb][nt][1] = fexp2(sv[mb][nt][1] - mn0); s0 += sv[mb][nt][1];
                    sv[mb][nt][2] = fexp2(sv[mb][nt][2] - mn1); s1 += sv[mb][nt][2];
                    sv[mb][nt][3] = fexp2(sv[mb][nt][3] - mn1); s1 += sv[mb][nt][3];
                }
                s0 += __shfl_xor_sync(0xffffffffu, s0, 1);
                s0 += __shfl_xor_sync(0xffffffffu, s0, 2);
                s1 += __shfl_xor_sync(0xffffffffu, s1, 1);
                s1 += __shfl_xor_sync(0xffffffffu, s1, 2);
                l_[g0] = l_[g0] * al0 + s0;  l_[g1] = l_[g1] * al1 + s1;
                m_[g0] = mn0;  m_[g1] = mn1;
#pragma unroll
                for (int nt = 0; nt < 8; nt++) {
                    o[mb][nt][0] *= al0; o[mb][nt][1] *= al0;
                    o[mb][nt][2] *= al1; o[mb][nt][3] *= al1;
                }
            }

            // ---- O += P V : P in registers, V fragments software-pipelined ----
#pragma unroll
            for (int ck = 0; ck < 4; ck++) {
                const int cur = ck & 1;
                if (ck < 3) {
                    const int k1 = (ck + 1) * 8;
#pragma unroll
                    for (int np = 0; np < 4; np++)
                        ldsm4(vf[cur ^ 1][np][0], vf[cur ^ 1][np][1],
                              vf[cur ^ 1][np][2], vf[cur ^ 1][np][3],
                              vb + (b_off + np * 16 * FS + k1) * 4);
                }
                uint32_t a[2][4];
#pragma unroll
                for (int mb = 0; mb < 2; mb++) {
                    a[mb][0] = f2h2(sv[mb][2*ck][0],   sv[mb][2*ck][1]);
                    a[mb][1] = f2h2(sv[mb][2*ck][2],   sv[mb][2*ck][3]);
                    a[mb][2] = f2h2(sv[mb][2*ck+1][0], sv[mb][2*ck+1][1]);
                    a[mb][3] = f2h2(sv[mb][2*ck+1][2], sv[mb][2*ck+1][3]);
                }
#pragma unroll
                for (int nt = 0; nt < 8; nt++) {
                    const uint32_t b0 = vf[cur][nt >> 1][(nt & 1) * 2];
                    const uint32_t b1 = vf[cur][nt >> 1][(nt & 1) * 2 + 1];
                    mma16(o[0][nt], a[0][0], a[0][1], a[0][2], a[0][3], b0, b1);
                    mma16(o[1][nt], a[1][0], a[1][1], a[1][2], a[1][3], b0, b1);
                }
            }
        }

        // ---- normalize + store (fp16) ----
#pragma unroll
        for (int mb = 0; mb < 2; mb++) {
            const float i0 = 1.0f / l_[2 * mb], i1 = 1.0f / l_[2 * mb + 1];
            const int r0 = qt * 128 + wm + mb * 16 + g, r1 = r0 + 8;
#pragma unroll
            for (int nt = 0; nt < 8; nt++) {
                const int c = h * HD + nt * 8 + tg * 2;
                *(uint32_t*)&O[(size_t)r0 * DM + c] = f2h2(o[mb][nt][0] * i0, o[mb][nt][1] * i0);
                *(uint32_t*)&O[(size_t)r1 * DM + c] = f2h2(o[mb][nt][2] * i1, o[mb][nt][3] * i1);
            }
        }
    }
}

// ================= launch =================
extern "C" void kernel_launch(void* const* d_in, const int* in_sizes, int n_in,
                              void* d_out, int out_size)
{
    (void)in_sizes; (void)n_in; (void)out_size;
    const float* x  = (const float*)d_in[0];
    const float* Wq = (const float*)d_in[1];
    const float* Wk = (const float*)d_in[2];
    const float* Wv = (const float*)d_in[3];
    const float* Wp = (const float*)d_in[4];
    float* out = (float*)d_out;

    __half *xh, *Qh, *Kh, *Vh, *Vt, *att;
    cudaGetSymbolAddress((void**)&xh,  g_xh);
    cudaGetSymbolAddress((void**)&Qh,  g_Qh);
    cudaGetSymbolAddress((void**)&Kh,  g_Kh);
    cudaGetSymbolAddress((void**)&Vh,  g_Vh);
    cudaGetSymbolAddress((void**)&Vt,  g_Vt);
    cudaGetSymbolAddress((void**)&att, g_att);

    const int flash_smem = FLASH_SMEM_WORDS * (int)sizeof(uint32_t);  // 55296 B
    cudaFuncSetAttribute(flash_tc, cudaFuncAttributeMaxDynamicSharedMemorySize, flash_smem);
    cudaFuncSetAttribute(gemm_qkv, cudaFuncAttributeMaxDynamicSharedMemorySize, GEMM_SMEM_BYTES);
    cudaFuncSetAttribute(gemm_proj, cudaFuncAttributeMaxDynamicSharedMemorySize, GEMM_SMEM_BYTES);

    // fp32 -> fp16 conversion of x + weights
    dim3 gc((SEQ * DM) / (256 * 8), 5);
    cvt_inputs<<<gc, 256>>>(x, Wq, Wk, Wv, Wp);

    // fused QKV projection (fp16 in/out, 4-stage cp.async)
    dim3 gq(DM / 128, SEQ / 128, 3);
    gemm_qkv<<<gq, 256, GEMM_SMEM_BYTES>>>(xh, Qh, Kh, Vh, SEQ, DM, DM);

    // transpose V -> fp16 [D][S] (+ reset flash work queue)
    dim3 gt(DM / 32, SEQ / 32);
    transpose_v<<<gt, 256>>>(Vh, Vt);

    // causal flash attention: persistent LPT queue, hoisted Q frags, pipelined V frags
    flash_tc<<<FLASH_GRID, 128, flash_smem>>>(Qh, Kh, Vt, att);

    // output projection (fp16 in, fp32 out, 4-stage cp.async)
    dim3 gp(DM / 128, SEQ / 128, 1);
    gemm_proj<<<gp, 256, GEMM_SMEM_BYTES>>>(att, out, SEQ, DM, DM);
}